// round 12
// baseline (speedup 1.0000x reference)
#include <cuda_runtime.h>
#include <cstdint>

#define B    4096
#define S    200
#define E    300
#define TAGS 2
#define EV4  75          // float4 per embedding row

#define TCTA 240         // transpose blocks (first)
#define PCTA 512         // pool blocks (8 rows each)
#define GCTA 256         // gemm blocks (16 rows each)
#define NT   128         // threads per block (all roles)

#define GM   16          // rows per gemm tile
#define NPAD 301         // conflict-free smem row stride (SCALAR access only)
#define NW   320         // padded N: 16 groups x 20
#define BK   10
#define NKT  30          // 300/10
#define TILE_F  (BK * NW)        // 3200 floats per tile
#define TILE_F4 (TILE_F / 4)     // 800 float4

// device scratch (zero-initialized at module load; flags return to 0 each run)
__device__ float g_pooled[B * E];
__device__ float g_w1t[E * NW];   // wt[k*NW+n] = w[n*E+k]; pads stay 0
__device__ float g_w2t[E * NW];
__device__ int   g_flag[GCTA];    // per gemm tile: # of pool CTAs done (0..2)
__device__ int   g_wflag;         // # transpose CTAs done (0..TCTA)
__device__ int   g_done;          // # gemm CTAs done (for wflag reset)

// ---------------- PTX helpers ----------------
__device__ __forceinline__ void cp16(uint32_t saddr, const void* g)
{ asm volatile("cp.async.cg.shared.global [%0], [%1], 16;" :: "r"(saddr), "l"(g)); }
__device__ __forceinline__ void cp_commit()
{ asm volatile("cp.async.commit_group;"); }

typedef unsigned long long u64;
__device__ __forceinline__ u64 pack2(float x)
{ u64 r; asm("mov.b64 %0, {%1, %1};" : "=l"(r) : "f"(x)); return r; }
__device__ __forceinline__ u64 fma2(u64 a, u64 b, u64 c)
{ u64 d; asm("fma.rn.f32x2 %0, %1, %2, %3;" : "=l"(d) : "l"(a), "l"(b), "l"(c)); return d; }
__device__ __forceinline__ float lo32(u64 v) { return __uint_as_float((uint32_t)(v & 0xffffffffull)); }
__device__ __forceinline__ float hi32(u64 v) { return __uint_as_float((uint32_t)(v >> 32)); }

// ---------------------------------------------------------------------------
// GEMM inner: 2 rows x 20 cols per thread, proven 2-sync double buffer (R11).
// ---------------------------------------------------------------------------
__device__ __forceinline__ void gemmT(
    const float* __restrict__ Wt,
    const float* __restrict__ s_a,
    float (*s_w)[TILE_F],
    int r0, int n0, int tid, u64 acc2[20])
{
#pragma unroll
    for (int j = 0; j < 20; ++j) acc2[j] = 0ull;

    const uint32_t sb0 = (uint32_t)__cvta_generic_to_shared(&s_w[0][0]);
    const uint32_t sb1 = (uint32_t)__cvta_generic_to_shared(&s_w[1][0]);

#pragma unroll
    for (int i = 0; i < 7; ++i) {
        const int idx = tid + i * NT;
        if (idx < TILE_F4) cp16(sb0 + idx * 16, Wt + idx * 4);
    }
    cp_commit();

    for (int kt = 0; kt < NKT; ++kt) {
        if (kt + 1 < NKT) {
            const uint32_t dst = ((kt + 1) & 1) ? sb1 : sb0;
            const float* src = Wt + (kt + 1) * TILE_F;
#pragma unroll
            for (int i = 0; i < 7; ++i) {
                const int idx = tid + i * NT;
                if (idx < TILE_F4) cp16(dst + idx * 16, src + idx * 4);
            }
            cp_commit();
            asm volatile("cp.async.wait_group 1;");   // my tile-kt copies done
        } else {
            asm volatile("cp.async.wait_group 0;");
        }
        __syncthreads();              // ALL threads' tile-kt copies visible

        const float* wb = s_w[kt & 1];
        const int kb = kt * BK;
#pragma unroll
        for (int kk = 0; kk < BK; ++kk) {
            const u64 a0 = pack2(s_a[r0 * NPAD + kb + kk]);        // scalar LDS
            const u64 a1 = pack2(s_a[(r0 + 1) * NPAD + kb + kk]);
            const ulonglong2* wr = (const ulonglong2*)(wb + kk * NW + n0);
#pragma unroll
            for (int j = 0; j < 5; ++j) {
                const ulonglong2 wv = wr[j];
                acc2[2*j + 0]      = fma2(a0, wv.x, acc2[2*j + 0]);
                acc2[2*j + 1]      = fma2(a0, wv.y, acc2[2*j + 1]);
                acc2[10 + 2*j + 0] = fma2(a1, wv.x, acc2[10 + 2*j + 0]);
                acc2[10 + 2*j + 1] = fma2(a1, wv.y, acc2[10 + 2*j + 1]);
            }
        }
        __syncthreads();              // buf kt free before next refill
    }
}

// ---------------------------------------------------------------------------
// One kernel, three roles, tile-level producer->consumer via L2 atomics.
// Block order: [0,TCTA) transpose, [TCTA,TCTA+PCTA) pool, rest gemm.
// ---------------------------------------------------------------------------
__global__ __launch_bounds__(NT) void fused_pipeline(
    const int*   __restrict__ x,
    const float* __restrict__ emb,
    const float* __restrict__ w1,
    const float* __restrict__ w2,
    const float* __restrict__ w3,
    float*       __restrict__ out)
{
    __shared__ float s_w[2][TILE_F];        // 25600 B (pool aliases as ids)
    __shared__ float s_a[GM * NPAD];        // 19264 B
    __shared__ float s_w3[TAGS * NW];       //  2560 B  (47424 B total)

    const int tid = threadIdx.x;
    const int bid = blockIdx.x;

    // ======================= TRANSPOSE (blocks 0..TCTA-1) ====================
    if (bid < TCTA) {
        const int total = E * E;
        const int start = bid * NT + tid;
        const int step  = TCTA * NT;
        for (int idx = start; idx < 2 * total; idx += step) {
            const int sel = idx / total;            // 0 -> w1, 1 -> w2
            const int e   = idx - sel * total;      // coalesced over n*E+k
            const int n = e / E, k = e % E;
            const float v = sel ? w2[e] : w1[e];
            if (sel) g_w2t[k * NW + n] = v;
            else     g_w1t[k * NW + n] = v;
        }
        __syncthreads();
        if (tid == 0) { __threadfence(); atomicAdd(&g_wflag, 1); }
        return;
    }

    // ======================= POOL (next PCTA blocks) =========================
    if (bid < TCTA + PCTA) {
        const int p  = bid - TCTA;
        const int b0 = p * 8;
        int* s_ids = (int*)&s_w[0][0];              // 1600 ints

        {
            const int4* src = (const int4*)(x + b0 * S);
            int4* dst = (int4*)s_ids;
#pragma unroll
            for (int i = 0; i < 4; ++i) {
                const int idx = tid + i * NT;
                if (idx < 8 * S / 4) dst[idx] = src[idx];
            }
        }
        __syncthreads();

        // warp w owns rows 2w, 2w+1 -> 6 independent load streams per warp
        const int w = tid >> 5, lane = tid & 31;
        const int m0 = 2 * w, m1 = m0 + 1;
        const bool has2 = lane < (EV4 - 64);        // lanes 0..10 own slot lane+64
        const float4* __restrict__ ev = (const float4*)emb;
        const int* __restrict__ rid0 = s_ids + m0 * S;
        const int* __restrict__ rid1 = s_ids + m1 * S;

        float4 a00 = {0,0,0,0}, a01 = {0,0,0,0}, a02 = {0,0,0,0};
        float4 a10 = {0,0,0,0}, a11 = {0,0,0,0}, a12 = {0,0,0,0};
#pragma unroll 2
        for (int t = 0; t < S; ++t) {
            const int i0 = rid0[t] * EV4;           // <= 37.5M, fits int32
            const int i1 = rid1[t] * EV4;
            float4 v;
            v = __ldg(ev + i0 + lane);      a00.x += v.x; a00.y += v.y; a00.z += v.z; a00.w += v.w;
            v = __ldg(ev + i0 + lane + 32); a01.x += v.x; a01.y += v.y; a01.z += v.z; a01.w += v.w;
            v = __ldg(ev + i1 + lane);      a10.x += v.x; a10.y += v.y; a10.z += v.z; a10.w += v.w;
            v = __ldg(ev + i1 + lane + 32); a11.x += v.x; a11.y += v.y; a11.z += v.z; a11.w += v.w;
            if (has2) {
                v = __ldg(ev + i0 + lane + 64); a02.x += v.x; a02.y += v.y; a02.z += v.z; a02.w += v.w;
                v = __ldg(ev + i1 + lane + 64); a12.x += v.x; a12.y += v.y; a12.z += v.z; a12.w += v.w;
            }
        }
        const float sc = 1.0f / (float)S;
        float4* p0 = (float4*)(g_pooled + (b0 + m0) * E);
        float4* p1 = (float4*)(g_pooled + (b0 + m1) * E);
        p0[lane]      = make_float4(a00.x*sc, a00.y*sc, a00.z*sc, a00.w*sc);
        p0[lane + 32] = make_float4(a01.x*sc, a01.y*sc, a01.z*sc, a01.w*sc);
        p1[lane]      = make_float4(a10.x*sc, a10.y*sc, a10.z*sc, a10.w*sc);
        p1[lane + 32] = make_float4(a11.x*sc, a11.y*sc, a11.z*sc, a11.w*sc);
        if (has2) {
            p0[lane + 64] = make_float4(a02.x*sc, a02.y*sc, a02.z*sc, a02.w*sc);
            p1[lane + 64] = make_float4(a12.x*sc, a12.y*sc, a12.z*sc, a12.w*sc);
        }
        __syncthreads();                            // all warps' stores issued
        if (tid == 0) { __threadfence(); atomicAdd(&g_flag[p >> 1], 1); }
        return;
    }

    // ======================= GEMM (last GCTA blocks) =========================
    const int i  = bid - TCTA - PCTA;
    const int b0 = i * GM;

    // wait: weights transposed + my 2 pool producers done (consume-and-reset)
    if (tid == 0) {
        while (atomicAdd(&g_wflag, 0) != TCTA) __nanosleep(200);
        while (atomicCAS(&g_flag[i], 2, 0) != 2) __nanosleep(200);
        __threadfence();                            // acquire
    }
    __syncthreads();

    // stage pooled rows (L2 reads via __ldcg: skip possibly-stale L1) + w3
    {
        const float4* src = (const float4*)(g_pooled + b0 * E);
#pragma unroll
        for (int k = 0; k < 10; ++k) {
            const int idx = tid + k * NT;           // 0..1199 float4
            if (idx < GM * E / 4) {
                const int m = idx / EV4, s = idx - m * EV4;
                const float4 v = __ldcg(&src[idx]);
                float* dst = &s_a[m * NPAD + s * 4];
                dst[0] = v.x; dst[1] = v.y; dst[2] = v.z; dst[3] = v.w;
            }
        }
#pragma unroll
        for (int k = 0; k < 5; ++k) {
            const int idx = tid + k * NT;
            if (idx < TAGS * NW) {
                const int t = idx / NW, n = idx % NW;
                s_w3[idx] = (n < E) ? w3[t * E + n] : 0.0f;
            }
        }
    }
    // first __syncthreads inside gemmT (post-wait) fences the staging stores

    const int r0 = (tid & 7) * 2;       // rows r0, r0+1
    const int g  = tid >> 3;            // 0..15
    const int n0 = g * 20;

    u64 acc2[20];

    // layer 1
    gemmT(g_w1t, s_a, s_w, r0, n0, tid, acc2);
#pragma unroll
    for (int r = 0; r < 2; ++r) {
#pragma unroll
        for (int j = 0; j < 10; ++j) {
            const int n = n0 + 2 * j;
            const u64 v = acc2[r * 10 + j];
            if (n     < E) s_a[(r0 + r) * NPAD + n]     = fmaxf(lo32(v), 0.0f);
            if (n + 1 < E) s_a[(r0 + r) * NPAD + n + 1] = fmaxf(hi32(v), 0.0f);
        }
    }
    // layer 2 (+fused head)
    gemmT(g_w2t, s_a, s_w, r0, n0, tid, acc2);

    float* s_part = &s_w[0][0];          // alias: all cp.async drained
#pragma unroll
    for (int r = 0; r < 2; ++r) {
        float s0 = 0.0f, s1 = 0.0f;
#pragma unroll
        for (int j = 0; j < 10; ++j) {
            const u64 v = acc2[r * 10 + j];
            const float lo = fmaxf(lo32(v), 0.0f);
            const float hi = fmaxf(hi32(v), 0.0f);
            s0 = fmaf(lo, s_w3[n0 + 2*j],          s0);
            s0 = fmaf(hi, s_w3[n0 + 2*j + 1],      s0);
            s1 = fmaf(lo, s_w3[NW + n0 + 2*j],     s1);
            s1 = fmaf(hi, s_w3[NW + n0 + 2*j + 1], s1);
        }
        s_part[((r0 + r) * 16 + g) * 2 + 0] = s0;
        s_part[((r0 + r) * 16 + g) * 2 + 1] = s1;
    }
    __syncthreads();

    if (tid < GM * TAGS) {
        const int mm = tid >> 1, t = tid & 1;
        float s = 0.0f;
#pragma unroll
        for (int gg = 0; gg < 16; ++gg)
            s += s_part[(mm * 16 + gg) * 2 + t];
        out[(b0 + mm) * TAGS + t] = s;
    }

    // last gemm CTA resets the transpose flag + done counter for replays
    if (tid == 0) {
        const int old = atomicAdd(&g_done, 1);
        if (old == GCTA - 1) {
            atomicExch(&g_wflag, 0);
            atomicExch(&g_done, 0);
        }
    }
}

// ---------------------------------------------------------------------------
// Launch: one kernel, blocks ordered transpose -> pool -> gemm.
// ---------------------------------------------------------------------------
extern "C" void kernel_launch(void* const* d_in, const int* in_sizes, int n_in,
                              void* d_out, int out_size)
{
    const int*   x   = (const int*)d_in[0];
    const float* emb = (const float*)d_in[1];
    const float* w1  = (const float*)d_in[2];
    const float* w2  = (const float*)d_in[3];
    const float* w3  = (const float*)d_in[4];
    float* out = (float*)d_out;

    fused_pipeline<<<TCTA + PCTA + GCTA, NT>>>(x, emb, w1, w2, w3, out);
}

// round 13
// speedup vs baseline: 1.1680x; 1.1680x over previous
#include <cuda_runtime.h>
#include <cstdint>

#define B    4096
#define S    200
#define E    300
#define TAGS 2
#define EV4  75          // float4 per embedding row

#define PCTA 512         // pool CTAs (8 rows each)
#define TCTA 120         // transpose CTAs (run concurrently)

#define GM   32          // rows per GEMM CTA
#define NT   128         // threads per GEMM CTA
#define NPAD 301         // conflict-free smem row stride (SCALAR access only)
#define NW   320         // padded N: 16 groups x 20
#define BK   10
#define NKT  30          // 300/10
#define TILE_F  (BK * NW)        // 3200 floats per tile
#define TILE_F4 (TILE_F / 4)     // 800 float4

// dynamic smem layout (floats)
#define OFF_A   (2 * TILE_F)
#define OFF_W3  (OFF_A + GM * NPAD)
#define SMEM_FLOATS (OFF_W3 + TAGS * NW)
#define SMEM_BYTES  (SMEM_FLOATS * 4)      // 66688 B

// device scratch
__device__ float g_pooled[B * E];
__device__ float g_w1t[E * NW];   // wt[k*NW+n] = w[n*E+k]; pads stay 0 (zero-init)
__device__ float g_w2t[E * NW];

// ---------------- PTX helpers ----------------
__device__ __forceinline__ void cp16(uint32_t saddr, const void* g)
{ asm volatile("cp.async.cg.shared.global [%0], [%1], 16;" :: "r"(saddr), "l"(g)); }
__device__ __forceinline__ void cp_commit()
{ asm volatile("cp.async.commit_group;"); }

typedef unsigned long long u64;
__device__ __forceinline__ u64 pack2(float x)
{ u64 r; asm("mov.b64 %0, {%1, %1};" : "=l"(r) : "f"(x)); return r; }
__device__ __forceinline__ u64 fma2(u64 a, u64 b, u64 c)
{ u64 d; asm("fma.rn.f32x2 %0, %1, %2, %3;" : "=l"(d) : "l"(a), "l"(b), "l"(c)); return d; }
__device__ __forceinline__ float lo32(u64 v) { return __uint_as_float((uint32_t)(v & 0xffffffffull)); }
__device__ __forceinline__ float hi32(u64 v) { return __uint_as_float((uint32_t)(v >> 32)); }

// ---------------------------------------------------------------------------
// Kernel 1: CTAs [0,512): gather+mean-pool, warp-per-row.
//           CTAs [512,512+120): transpose+pad W1,W2 (hidden under the gather).
// (unchanged from R11 — measured at the HBM random-row floor)
// ---------------------------------------------------------------------------
__global__ __launch_bounds__(256) void pool_and_prep(
    const int*   __restrict__ x,
    const float* __restrict__ emb,
    const float* __restrict__ w1,
    const float* __restrict__ w2)
{
    if (blockIdx.x >= PCTA) {
        const int total = E * E;
        const int start = (blockIdx.x - PCTA) * 256 + threadIdx.x;
        const int step  = TCTA * 256;
        for (int idx = start; idx < 2 * total; idx += step) {
            const int sel = idx / total;            // 0 -> w1, 1 -> w2
            const int e   = idx - sel * total;      // coalesced over n*E+k
            const int n = e / E, k = e % E;
            const float v = sel ? w2[e] : w1[e];
            if (sel) g_w2t[k * NW + n] = v;
            else     g_w1t[k * NW + n] = v;
        }
        return;
    }

    __shared__ int s_ids[8 * S];
    const int b0 = blockIdx.x * 8;
    {
        const int4* src = (const int4*)(x + b0 * S);
        int4* dst = (int4*)s_ids;
#pragma unroll
        for (int i = 0; i < 2; ++i) {
            const int idx = threadIdx.x + i * 256;
            if (idx < 8 * S / 4) dst[idx] = src[idx];
        }
    }
    __syncthreads();

    const int w = threadIdx.x >> 5, lane = threadIdx.x & 31;
    const bool has2 = lane < (EV4 - 64);            // lanes 0..10 own slot lane+64
    const float4* __restrict__ ev = (const float4*)emb;
    const int* __restrict__ rid = s_ids + w * S;

    float4 a0 = {0,0,0,0}, a1 = {0,0,0,0}, a2 = {0,0,0,0};
#pragma unroll 4
    for (int t = 0; t < S; ++t) {
        const int base = rid[t] * EV4;              // <= 37.5M, fits int32
        float4 v0 = __ldg(ev + base + lane);
        float4 v1 = __ldg(ev + base + lane + 32);
        a0.x += v0.x; a0.y += v0.y; a0.z += v0.z; a0.w += v0.w;
        a1.x += v1.x; a1.y += v1.y; a1.z += v1.z; a1.w += v1.w;
        if (has2) {
            float4 v2 = __ldg(ev + base + lane + 64);
            a2.x += v2.x; a2.y += v2.y; a2.z += v2.z; a2.w += v2.w;
        }
    }
    const float sc = 1.0f / (float)S;
    float4* p = (float4*)(g_pooled + (b0 + w) * E);
    p[lane]      = make_float4(a0.x*sc, a0.y*sc, a0.z*sc, a0.w*sc);
    p[lane + 32] = make_float4(a1.x*sc, a1.y*sc, a1.z*sc, a1.w*sc);
    if (has2)
        p[lane + 64] = make_float4(a2.x*sc, a2.y*sc, a2.z*sc, a2.w*sc);
}

// ---------------------------------------------------------------------------
// One layer, 4 rows x 20 cols per thread (w loads amortized over 4 rows):
//   acc2[r*10 + j] : row r0+r, col pair n0+2j (f32x2)
// Wt pretransposed [300][NW]. PROVEN 2-sync double-buffer pipeline.
// All NT threads must call (uniform).
// ---------------------------------------------------------------------------
__device__ __forceinline__ void gemmT(
    const float* __restrict__ Wt,
    const float* __restrict__ s_a,
    float* __restrict__ s_w,            // 2 tiles
    int r0, int n0, int tid, u64 acc2[40])
{
#pragma unroll
    for (int j = 0; j < 40; ++j) acc2[j] = 0ull;

    const uint32_t sb0 = (uint32_t)__cvta_generic_to_shared(s_w);
    const uint32_t sb1 = sb0 + TILE_F * 4;

    // prologue: tile 0 -> buf 0
#pragma unroll
    for (int i = 0; i < 7; ++i) {
        const int idx = tid + i * NT;
        if (idx < TILE_F4) cp16(sb0 + idx * 16, Wt + idx * 4);
    }
    cp_commit();

    for (int kt = 0; kt < NKT; ++kt) {
        if (kt + 1 < NKT) {
            const uint32_t dst = ((kt + 1) & 1) ? sb1 : sb0;
            const float* src = Wt + (kt + 1) * TILE_F;
#pragma unroll
            for (int i = 0; i < 7; ++i) {
                const int idx = tid + i * NT;
                if (idx < TILE_F4) cp16(dst + idx * 16, src + idx * 4);
            }
            cp_commit();
            asm volatile("cp.async.wait_group 1;");   // my tile-kt copies done
        } else {
            asm volatile("cp.async.wait_group 0;");
        }
        __syncthreads();              // ALL threads' tile-kt copies visible

        const float* wb = s_w + (kt & 1) * TILE_F;
        const int kb = kt * BK;
#pragma unroll
        for (int kk = 0; kk < BK; ++kk) {
            u64 a[4];
#pragma unroll
            for (int r = 0; r < 4; ++r)
                a[r] = pack2(s_a[(r0 + r) * NPAD + kb + kk]);    // scalar LDS
            // offset (kk*NW + n0) floats = kk*1280 + 80g bytes -> 16B aligned
            const ulonglong2* wr = (const ulonglong2*)(wb + kk * NW + n0);
#pragma unroll
            for (int j = 0; j < 5; ++j) {
                const ulonglong2 wv = wr[j];
#pragma unroll
                for (int r = 0; r < 4; ++r) {
                    acc2[r * 10 + 2*j + 0] = fma2(a[r], wv.x, acc2[r * 10 + 2*j + 0]);
                    acc2[r * 10 + 2*j + 1] = fma2(a[r], wv.y, acc2[r * 10 + 2*j + 1]);
                }
            }
        }
        __syncthreads();              // buf kt free before next refill
    }
}

// ---------------------------------------------------------------------------
// Kernel 2: 32 rows/CTA, 128 threads, grid 128, 4 rows x 20 cols per thread:
//   relu(relu(pooled W1^T) W2^T) W3^T -> out
// ---------------------------------------------------------------------------
__global__ __launch_bounds__(NT) void gemm_head(
    const float* __restrict__ pooled,
    const float* __restrict__ w3,
    float*       __restrict__ out)
{
    extern __shared__ float smem[];
    float* s_w  = smem;                 // 2 tiles, 16B-aligned base
    float* s_a  = smem + OFF_A;
    float* s_w3 = smem + OFF_W3;
    float* s_part = s_w;                // alias after all cp.async drained

    const int tid = threadIdx.x;
    const int b0  = blockIdx.x * GM;

    // stage pooled rows (vector gmem load, SCALAR smem stores: NPAD rows only
    // 4B-aligned) + padded w3
    {
        const float4* src = (const float4*)(pooled + b0 * E);
#pragma unroll
        for (int i = 0; i < 19; ++i) {
            const int idx = tid + i * NT;        // 0..2399 float4
            if (idx < GM * E / 4) {
                const int m = idx / EV4, s = idx - m * EV4;
                const float4 v = src[idx];
                float* dst = &s_a[m * NPAD + s * 4];
                dst[0] = v.x; dst[1] = v.y; dst[2] = v.z; dst[3] = v.w;
            }
        }
#pragma unroll
        for (int i = 0; i < 5; ++i) {
            const int idx = tid + i * NT;
            if (idx < TAGS * NW) {
                const int t = idx / NW, n = idx % NW;
                s_w3[idx] = (n < E) ? w3[t * E + n] : 0.0f;
            }
        }
    }
    // first __syncthreads inside gemmT (post-wait) fences the staging stores

    const int r0 = (tid & 7) * 4;       // rows r0..r0+3
    const int g  = tid >> 3;            // 0..15
    const int n0 = g * 20;

    u64 acc2[40];

    // layer 1
    gemmT(g_w1t, s_a, s_w, r0, n0, tid, acc2);
    // gemmT ends with __syncthreads: all layer-1 reads of s_a complete
#pragma unroll
    for (int r = 0; r < 4; ++r) {
#pragma unroll
        for (int j = 0; j < 10; ++j) {
            const int n = n0 + 2 * j;
            const u64 v = acc2[r * 10 + j];
            if (n     < E) s_a[(r0 + r) * NPAD + n]     = fmaxf(lo32(v), 0.0f);
            if (n + 1 < E) s_a[(r0 + r) * NPAD + n + 1] = fmaxf(hi32(v), 0.0f);
        }
    }
    // layer 2 (+fused head); first post-wait sync inside orders the h1 stores
    gemmT(g_w2t, s_a, s_w, r0, n0, tid, acc2);

#pragma unroll
    for (int r = 0; r < 4; ++r) {
        float s0 = 0.0f, s1 = 0.0f;
#pragma unroll
        for (int j = 0; j < 10; ++j) {
            const u64 v = acc2[r * 10 + j];
            const float lo = fmaxf(lo32(v), 0.0f);      // pad cols: w=0 -> acc=0
            const float hi = fmaxf(hi32(v), 0.0f);
            s0 = fmaf(lo, s_w3[n0 + 2*j],          s0);
            s0 = fmaf(hi, s_w3[n0 + 2*j + 1],      s0);
            s1 = fmaf(lo, s_w3[NW + n0 + 2*j],     s1);
            s1 = fmaf(hi, s_w3[NW + n0 + 2*j + 1], s1);
        }
        // gemmT's trailing __syncthreads: all compute done, cp.async drained
        s_part[((r0 + r) * 16 + g) * 2 + 0] = s0;
        s_part[((r0 + r) * 16 + g) * 2 + 1] = s1;
    }
    __syncthreads();

    if (tid < GM * TAGS) {
        const int mm = tid >> 1, t = tid & 1;
        float s = 0.0f;
#pragma unroll
        for (int gg = 0; gg < 16; ++gg)
            s += s_part[(mm * 16 + gg) * 2 + t];
        out[(b0 + mm) * TAGS + t] = s;
    }
}

// ---------------------------------------------------------------------------
// Launch
// ---------------------------------------------------------------------------
extern "C" void kernel_launch(void* const* d_in, const int* in_sizes, int n_in,
                              void* d_out, int out_size)
{
    const int*   x   = (const int*)d_in[0];
    const float* emb = (const float*)d_in[1];
    const float* w1  = (const float*)d_in[2];
    const float* w2  = (const float*)d_in[3];
    const float* w3  = (const float*)d_in[4];
    float* out = (float*)d_out;

    float* pooled; cudaGetSymbolAddress((void**)&pooled, g_pooled);

    cudaFuncSetAttribute(gemm_head,
                         cudaFuncAttributeMaxDynamicSharedMemorySize, SMEM_BYTES);

    pool_and_prep<<<PCTA + TCTA, 256>>>(x, emb, w1, w2);
    gemm_head<<<B / GM, NT, SMEM_BYTES>>>(pooled, w3, out);
}